// round 2
// baseline (speedup 1.0000x reference)
#include <cuda_runtime.h>
#include <math.h>

// ---------------------------------------------------------------------------
// Problem constants
// ---------------------------------------------------------------------------
#define BATCH 2
#define D 256
#define NH 8
#define DH 32
#define NL 4
#define NP 4
#define NLAYERS 6
#define DFF 1024
#define S_TOTAL 21760
#define M_ROWS (BATCH * S_TOTAL)   // 43520

// level shapes (square): 128,64,32,16
__device__ __constant__ int c_lvl_h[NL]     = {128, 64, 32, 16};
__device__ __constant__ int c_lvl_w[NL]     = {128, 64, 32, 16};
__device__ __constant__ int c_lvl_start[NL] = {0, 16384, 20480, 21504};

// ---------------------------------------------------------------------------
// Scratch buffers (device globals — no allocation allowed)
// ---------------------------------------------------------------------------
__device__ float g_pos    [(size_t)M_ROWS * D];
__device__ float g_out    [(size_t)M_ROWS * D];
__device__ float g_q      [(size_t)M_ROWS * D];
__device__ float g_value  [(size_t)M_ROWS * D];
__device__ float g_off    [(size_t)M_ROWS * 256];
__device__ float g_attn   [(size_t)M_ROWS * 128];
__device__ float g_attnout[(size_t)M_ROWS * D];
__device__ float g_proj   [(size_t)M_ROWS * D];
__device__ float g_ffn1   [(size_t)M_ROWS * DFF];
__device__ float g_ffn2   [(size_t)M_ROWS * D];

// ---------------------------------------------------------------------------
// helpers
// ---------------------------------------------------------------------------
__device__ __forceinline__ void level_of_s(int s, int& lvl, int& start, int& hh, int& ww) {
    if (s < 16384)      { lvl = 0; start = 0;     hh = 128; ww = 128; }
    else if (s < 20480) { lvl = 1; start = 16384; hh = 64;  ww = 64;  }
    else if (s < 21504) { lvl = 2; start = 20480; hh = 32;  ww = 32;  }
    else                { lvl = 3; start = 21504; hh = 16;  ww = 16;  }
}

// ---------------------------------------------------------------------------
// 1. Flatten srcs/pos into [B, S, D] row-major + level embed
// ---------------------------------------------------------------------------
__global__ void flatten_kernel(const float* __restrict__ s0, const float* __restrict__ s1,
                               const float* __restrict__ s2, const float* __restrict__ s3,
                               const float* __restrict__ p0, const float* __restrict__ p1,
                               const float* __restrict__ p2, const float* __restrict__ p3,
                               const float* __restrict__ le) {
    size_t idx = (size_t)blockIdx.x * blockDim.x + threadIdx.x;
    size_t total = (size_t)M_ROWS * D;
    if (idx >= total) return;
    int d = (int)(idx % D);
    int bs = (int)(idx / D);
    int s = bs % S_TOTAL;
    int b = bs / S_TOTAL;
    int lvl, start, hh, ww;
    level_of_s(s, lvl, start, hh, ww);
    int local = s - start;
    int y = local / ww;
    int x = local % ww;
    const float* sp; const float* pp;
    switch (lvl) {
        case 0: sp = s0; pp = p0; break;
        case 1: sp = s1; pp = p1; break;
        case 2: sp = s2; pp = p2; break;
        default: sp = s3; pp = p3; break;
    }
    size_t off = (((size_t)b * D + d) * hh + y) * ww + x;
    g_out[idx] = sp[off];
    g_pos[idx] = pp[off] + le[lvl * D + d];
}

// ---------------------------------------------------------------------------
// 2. q = out + pos
// ---------------------------------------------------------------------------
__global__ void add_kernel() {
    size_t idx = (size_t)blockIdx.x * blockDim.x + threadIdx.x;
    size_t total = (size_t)M_ROWS * D;
    if (idx >= total) return;
    g_q[idx] = g_out[idx] + g_pos[idx];
}

// ---------------------------------------------------------------------------
// 3. SGEMM: C[M,N] = A[M,K] @ B[K,N] + bias, optional ReLU
//    BM=BN=128, BK=8, 256 threads, 8x8 per thread.
//    Requires M%128==0, N%128==0, K%8==0 (true for all our GEMMs).
// ---------------------------------------------------------------------------
template <bool RELU>
__global__ __launch_bounds__(256, 2)
void sgemm_kernel(const float* __restrict__ A, const float* __restrict__ B,
                  const float* __restrict__ bias, float* __restrict__ C,
                  int Mdim, int Ndim, int Kdim) {
    __shared__ float As[8][128];
    __shared__ float Bs[8][128];

    const int tid = threadIdx.x;
    const int bm = blockIdx.y * 128;
    const int bn = blockIdx.x * 128;

    const int a_row  = tid >> 1;
    const int a_col4 = (tid & 1) * 4;
    const int b_row  = tid >> 5;
    const int b_col4 = (tid & 31) * 4;

    const int tx = tid & 15;   // 0..15 -> 8 cols each
    const int ty = tid >> 4;   // 0..15 -> 8 rows each

    float acc[8][8];
    #pragma unroll
    for (int i = 0; i < 8; ++i)
        #pragma unroll
        for (int j = 0; j < 8; ++j) acc[i][j] = 0.f;

    const float* Aload = A + (size_t)(bm + a_row) * Kdim + a_col4;
    const float* Bload = B + (size_t)b_row * Ndim + bn + b_col4;

    for (int kt = 0; kt < Kdim; kt += 8) {
        float4 av = *reinterpret_cast<const float4*>(Aload + kt);
        As[a_col4 + 0][a_row] = av.x;
        As[a_col4 + 1][a_row] = av.y;
        As[a_col4 + 2][a_row] = av.z;
        As[a_col4 + 3][a_row] = av.w;
        float4 bv = *reinterpret_cast<const float4*>(Bload + (size_t)kt * Ndim);
        *reinterpret_cast<float4*>(&Bs[b_row][b_col4]) = bv;
        __syncthreads();

        #pragma unroll
        for (int k = 0; k < 8; ++k) {
            float rA[8], rB[8];
            *reinterpret_cast<float4*>(rA)     = *reinterpret_cast<const float4*>(&As[k][ty * 8]);
            *reinterpret_cast<float4*>(rA + 4) = *reinterpret_cast<const float4*>(&As[k][ty * 8 + 4]);
            *reinterpret_cast<float4*>(rB)     = *reinterpret_cast<const float4*>(&Bs[k][tx * 8]);
            *reinterpret_cast<float4*>(rB + 4) = *reinterpret_cast<const float4*>(&Bs[k][tx * 8 + 4]);
            #pragma unroll
            for (int i = 0; i < 8; ++i)
                #pragma unroll
                for (int j = 0; j < 8; ++j)
                    acc[i][j] = fmaf(rA[i], rB[j], acc[i][j]);
        }
        __syncthreads();
    }

    float bb[8];
    #pragma unroll
    for (int j = 0; j < 8; ++j) bb[j] = bias[bn + tx * 8 + j];

    #pragma unroll
    for (int i = 0; i < 8; ++i) {
        int row = bm + ty * 8 + i;
        float* crow = C + (size_t)row * Ndim + bn + tx * 8;
        float4 c0, c1;
        float v;
        v = acc[i][0] + bb[0]; c0.x = RELU ? fmaxf(v, 0.f) : v;
        v = acc[i][1] + bb[1]; c0.y = RELU ? fmaxf(v, 0.f) : v;
        v = acc[i][2] + bb[2]; c0.z = RELU ? fmaxf(v, 0.f) : v;
        v = acc[i][3] + bb[3]; c0.w = RELU ? fmaxf(v, 0.f) : v;
        v = acc[i][4] + bb[4]; c1.x = RELU ? fmaxf(v, 0.f) : v;
        v = acc[i][5] + bb[5]; c1.y = RELU ? fmaxf(v, 0.f) : v;
        v = acc[i][6] + bb[6]; c1.z = RELU ? fmaxf(v, 0.f) : v;
        v = acc[i][7] + bb[7]; c1.w = RELU ? fmaxf(v, 0.f) : v;
        *reinterpret_cast<float4*>(crow)     = c0;
        *reinterpret_cast<float4*>(crow + 4) = c1;
    }
}

// ---------------------------------------------------------------------------
// 4. softmax over 16 logits per (b,s,h), in place in g_attn
// ---------------------------------------------------------------------------
__global__ void softmax16_kernel() {
    int idx = blockIdx.x * blockDim.x + threadIdx.x;   // (b*S+s)*NH + h
    if (idx >= M_ROWS * NH) return;
    int bs = idx >> 3;
    int h = idx & 7;
    float* p = g_attn + (size_t)bs * 128 + h * 16;
    float v[16];
    float mx = -1e30f;
    #pragma unroll
    for (int i = 0; i < 16; ++i) { v[i] = p[i]; mx = fmaxf(mx, v[i]); }
    float sum = 0.f;
    #pragma unroll
    for (int i = 0; i < 16; ++i) { v[i] = expf(v[i] - mx); sum += v[i]; }
    float inv = 1.f / sum;
    #pragma unroll
    for (int i = 0; i < 16; ++i) p[i] = v[i] * inv;
}

// ---------------------------------------------------------------------------
// 5. MS-deform sampling: warp per (b,s,h), lane = channel dh
// ---------------------------------------------------------------------------
__global__ __launch_bounds__(256)
void sample_kernel() {
    int warp = (blockIdx.x * blockDim.x + threadIdx.x) >> 5;
    int lane = threadIdx.x & 31;
    if (warp >= M_ROWS * NH) return;
    int h = warp & 7;
    int bs = warp >> 3;
    int b = bs / S_TOTAL;
    int s = bs - b * S_TOTAL;

    int qlvl, qstart, qh, qw;
    level_of_s(s, qlvl, qstart, qh, qw);
    int qlocal = s - qstart;
    int qy = qlocal / qw;
    int qx = qlocal - qy * qw;
    float ref_x = (qx + 0.5f) / (float)qw;
    float ref_y = (qy + 0.5f) / (float)qh;

    const float* offp = g_off  + (size_t)bs * 256 + h * 32;  // [NL][NP][2]
    const float* awp  = g_attn + (size_t)bs * 128 + h * 16;  // [NL][NP]
    const float* valb = g_value + (size_t)b * S_TOTAL * D + h * DH + lane;

    float acc = 0.f;
    #pragma unroll
    for (int l = 0; l < NL; ++l) {
        int H = c_lvl_h[l], W = c_lvl_w[l], start = c_lvl_start[l];
        float fW = (float)W, fH = (float)H;
        #pragma unroll
        for (int p = 0; p < NP; ++p) {
            float ox = offp[l * 8 + p * 2 + 0];
            float oy = offp[l * 8 + p * 2 + 1];
            float aw = awp[l * 4 + p];
            float x = (ref_x + ox / fW) * fW - 0.5f;
            float y = (ref_y + oy / fH) * fH - 0.5f;
            float x0f = floorf(x), y0f = floorf(y);
            float lx = x - x0f, ly = y - y0f;
            int x0 = (int)x0f, y0 = (int)y0f;
            int x1 = x0 + 1, y1 = y0 + 1;
            bool vx0 = (x0 >= 0) & (x0 < W);
            bool vx1 = (x1 >= 0) & (x1 < W);
            bool vy0 = (y0 >= 0) & (y0 < H);
            bool vy1 = (y1 >= 0) & (y1 < H);
            float v00 = 0.f, v10 = 0.f, v01 = 0.f, v11 = 0.f;
            if (vx0 & vy0) v00 = valb[(size_t)(start + y0 * W + x0) * D];
            if (vx1 & vy0) v10 = valb[(size_t)(start + y0 * W + x1) * D];
            if (vx0 & vy1) v01 = valb[(size_t)(start + y1 * W + x0) * D];
            if (vx1 & vy1) v11 = valb[(size_t)(start + y1 * W + x1) * D];
            float samp = (1.f - lx) * (1.f - ly) * v00
                       + lx * (1.f - ly) * v10
                       + (1.f - lx) * ly * v01
                       + lx * ly * v11;
            acc = fmaf(aw, samp, acc);
        }
    }
    g_attnout[(size_t)bs * D + h * DH + lane] = acc;
}

// ---------------------------------------------------------------------------
// 6. dst = LayerNorm(x + y) * gamma + beta    (warp per row of 256)
// ---------------------------------------------------------------------------
__global__ __launch_bounds__(256)
void residual_ln_kernel(const float* __restrict__ x, const float* __restrict__ y,
                        const float* __restrict__ gamma, const float* __restrict__ beta,
                        float* __restrict__ dst) {
    int row = (blockIdx.x * blockDim.x + threadIdx.x) >> 5;
    int lane = threadIdx.x & 31;
    if (row >= M_ROWS) return;
    const float* xr = x + (size_t)row * D + lane * 8;
    const float* yr = y + (size_t)row * D + lane * 8;
    float v[8];
    float s = 0.f;
    #pragma unroll
    for (int i = 0; i < 8; ++i) { v[i] = xr[i] + yr[i]; s += v[i]; }
    #pragma unroll
    for (int o = 16; o > 0; o >>= 1) s += __shfl_xor_sync(0xffffffffu, s, o);
    float mean = s * (1.f / D);
    float vs = 0.f;
    #pragma unroll
    for (int i = 0; i < 8; ++i) { float d = v[i] - mean; vs += d * d; }
    #pragma unroll
    for (int o = 16; o > 0; o >>= 1) vs += __shfl_xor_sync(0xffffffffu, vs, o);
    float rstd = rsqrtf(vs * (1.f / D) + 1e-5f);
    float* dr = dst + (size_t)row * D + lane * 8;
    #pragma unroll
    for (int i = 0; i < 8; ++i) {
        int c = lane * 8 + i;
        dr[i] = (v[i] - mean) * rstd * gamma[c] + beta[c];
    }
}

// ---------------------------------------------------------------------------
// host launcher
// ---------------------------------------------------------------------------
extern "C" void kernel_launch(void* const* d_in, const int* in_sizes, int n_in,
                              void* d_out, int out_size) {
    // ---- Resolve src/pos pointers by SIZE among the first 8 inputs. ----
    // setup_inputs() inserts src{l}, pos{l} interleaved; a grouped ordering is
    // also conceivable. Per-level sizes are unique (2*256*h*w), and src_l is
    // always inserted before pos_l, so: first match = src, second = pos.
    const int lvl_elems[NL] = {
        BATCH * D * 128 * 128,   // 8388608
        BATCH * D * 64 * 64,     // 2097152
        BATCH * D * 32 * 32,     // 524288
        BATCH * D * 16 * 16      // 131072
    };
    const float* srcp[NL] = {0, 0, 0, 0};
    const float* posp[NL] = {0, 0, 0, 0};
    for (int i = 0; i < 8; ++i) {
        int sz = in_sizes[i];
        for (int l = 0; l < NL; ++l) {
            if (sz == lvl_elems[l]) {
                if (!srcp[l]) srcp[l] = (const float*)d_in[i];
                else if (!posp[l]) posp[l] = (const float*)d_in[i];
                break;
            }
        }
    }

    const float* level_embed = (const float*)d_in[8];
    const float* Woff  = (const float*)d_in[9];
    const float* boff  = (const float*)d_in[10];
    const float* Wattn = (const float*)d_in[11];
    const float* battn = (const float*)d_in[12];
    const float* Wval  = (const float*)d_in[13];
    const float* bval  = (const float*)d_in[14];
    const float* Wout  = (const float*)d_in[15];
    const float* bout  = (const float*)d_in[16];
    const float* ln1_s = (const float*)d_in[17];
    const float* ln1_b = (const float*)d_in[18];
    const float* W1    = (const float*)d_in[19];
    const float* b1    = (const float*)d_in[20];
    const float* W2    = (const float*)d_in[21];
    const float* b2    = (const float*)d_in[22];
    const float* ln2_s = (const float*)d_in[23];
    const float* ln2_b = (const float*)d_in[24];
    float* out = (float*)d_out;

    float *p_pos, *p_out, *p_q, *p_value, *p_off, *p_attn, *p_attnout, *p_proj, *p_ffn1, *p_ffn2;
    cudaGetSymbolAddress((void**)&p_pos, g_pos);
    cudaGetSymbolAddress((void**)&p_out, g_out);
    cudaGetSymbolAddress((void**)&p_q, g_q);
    cudaGetSymbolAddress((void**)&p_value, g_value);
    cudaGetSymbolAddress((void**)&p_off, g_off);
    cudaGetSymbolAddress((void**)&p_attn, g_attn);
    cudaGetSymbolAddress((void**)&p_attnout, g_attnout);
    cudaGetSymbolAddress((void**)&p_proj, g_proj);
    cudaGetSymbolAddress((void**)&p_ffn1, g_ffn1);
    cudaGetSymbolAddress((void**)&p_ffn2, g_ffn2);

    const size_t total = (size_t)M_ROWS * D;
    const int TB = 256;
    const int elem_blocks = (int)((total + TB - 1) / TB);

    flatten_kernel<<<elem_blocks, TB>>>(srcp[0], srcp[1], srcp[2], srcp[3],
                                        posp[0], posp[1], posp[2], posp[3], level_embed);

    dim3 gemm_block(256);

    for (int i = 0; i < NLAYERS; ++i) {
        // q = out + pos
        add_kernel<<<elem_blocks, TB>>>();

        // value = out @ Wval[i] + bval[i]           [M,256]x[256,256]
        {
            dim3 grid(256 / 128, M_ROWS / 128);
            sgemm_kernel<false><<<grid, gemm_block>>>(p_out, Wval + (size_t)i * 256 * 256,
                                                      bval + (size_t)i * 256, p_value,
                                                      M_ROWS, 256, 256);
        }
        // off = q @ Woff[i] + boff[i]               [M,256]x[256,256]
        {
            dim3 grid(256 / 128, M_ROWS / 128);
            sgemm_kernel<false><<<grid, gemm_block>>>(p_q, Woff + (size_t)i * 256 * 256,
                                                      boff + (size_t)i * 256, p_off,
                                                      M_ROWS, 256, 256);
        }
        // attn logits = q @ Wattn[i] + battn[i]     [M,256]x[256,128]
        {
            dim3 grid(128 / 128, M_ROWS / 128);
            sgemm_kernel<false><<<grid, gemm_block>>>(p_q, Wattn + (size_t)i * 256 * 128,
                                                      battn + (size_t)i * 128, p_attn,
                                                      M_ROWS, 128, 256);
        }
        // softmax over 16
        {
            int n = M_ROWS * NH;
            softmax16_kernel<<<(n + TB - 1) / TB, TB>>>();
        }
        // deform sampling
        {
            int nwarps = M_ROWS * NH;
            int blocks = (nwarps * 32 + TB - 1) / TB;
            sample_kernel<<<blocks, TB>>>();
        }
        // proj = attnout @ Wout[i] + bout[i]
        {
            dim3 grid(256 / 128, M_ROWS / 128);
            sgemm_kernel<false><<<grid, gemm_block>>>(p_attnout, Wout + (size_t)i * 256 * 256,
                                                      bout + (size_t)i * 256, p_proj,
                                                      M_ROWS, 256, 256);
        }
        // out = LN(out + proj)
        {
            int blocks = (M_ROWS * 32 + TB - 1) / TB;
            residual_ln_kernel<<<blocks, TB>>>(p_out, p_proj,
                                               ln1_s + (size_t)i * 256, ln1_b + (size_t)i * 256,
                                               p_out);
        }
        // ffn1 = relu(out @ W1[i] + b1[i])          [M,256]x[256,1024]
        {
            dim3 grid(DFF / 128, M_ROWS / 128);
            sgemm_kernel<true><<<grid, gemm_block>>>(p_out, W1 + (size_t)i * 256 * DFF,
                                                     b1 + (size_t)i * DFF, p_ffn1,
                                                     M_ROWS, DFF, 256);
        }
        // ffn2 = ffn1 @ W2[i] + b2[i]               [M,1024]x[1024,256]
        {
            dim3 grid(256 / 128, M_ROWS / 128);
            sgemm_kernel<false><<<grid, gemm_block>>>(p_ffn1, W2 + (size_t)i * DFF * 256,
                                                      b2 + (size_t)i * 256, p_ffn2,
                                                      M_ROWS, 256, DFF);
        }
        // out = LN(out + ffn2)  (final layer writes straight to d_out)
        {
            float* dst = (i == NLAYERS - 1) ? out : p_out;
            int blocks = (M_ROWS * 32 + TB - 1) / TB;
            residual_ln_kernel<<<blocks, TB>>>(p_out, p_ffn2,
                                               ln2_s + (size_t)i * 256, ln2_b + (size_t)i * 256,
                                               dst);
        }
    }
}

// round 4
// speedup vs baseline: 1.9462x; 1.9462x over previous
#include <cuda_runtime.h>
#include <cuda_bf16.h>
#include <stdint.h>
#include <math.h>

// ---------------------------------------------------------------------------
// Problem constants
// ---------------------------------------------------------------------------
#define BATCH 2
#define D 256
#define NH 8
#define DH 32
#define NL 4
#define NP 4
#define NLAYERS 6
#define DFF 1024
#define S_TOTAL 21760
#define M_ROWS (BATCH * S_TOTAL)   // 43520

__device__ __constant__ int c_lvl_h[NL]     = {128, 64, 32, 16};
__device__ __constant__ int c_lvl_w[NL]     = {128, 64, 32, 16};
__device__ __constant__ int c_lvl_start[NL] = {0, 16384, 20480, 21504};

// ---------------------------------------------------------------------------
// Scratch buffers (device globals)
// ---------------------------------------------------------------------------
__device__ __align__(128) float g_pos    [(size_t)M_ROWS * D];
__device__ __align__(128) float g_out    [(size_t)M_ROWS * D];
__device__ __align__(128) float g_value  [(size_t)M_ROWS * D];
__device__ __align__(128) float g_offattn[(size_t)M_ROWS * 384];
__device__ __align__(128) float g_proj   [(size_t)M_ROWS * D];
__device__ __align__(128) float g_ffn2   [(size_t)M_ROWS * D];

// bf16 hi/lo activation buffers
__device__ __align__(128) __nv_bfloat16 g_out_hi [(size_t)M_ROWS * D];
__device__ __align__(128) __nv_bfloat16 g_out_lo [(size_t)M_ROWS * D];
__device__ __align__(128) __nv_bfloat16 g_q_hi   [(size_t)M_ROWS * D];
__device__ __align__(128) __nv_bfloat16 g_q_lo   [(size_t)M_ROWS * D];
__device__ __align__(128) __nv_bfloat16 g_ln1_hi [(size_t)M_ROWS * D];
__device__ __align__(128) __nv_bfloat16 g_ln1_lo [(size_t)M_ROWS * D];
__device__ __align__(128) __nv_bfloat16 g_attn_hi[(size_t)M_ROWS * D];
__device__ __align__(128) __nv_bfloat16 g_attn_lo[(size_t)M_ROWS * D];
__device__ __align__(128) __nv_bfloat16 g_f1_hi  [(size_t)M_ROWS * DFF];
__device__ __align__(128) __nv_bfloat16 g_f1_lo  [(size_t)M_ROWS * DFF];

// Preprocessed weights: transposed [N,K], bf16 hi/lo split
__device__ __align__(128) __nv_bfloat16 g_WvalT_hi [NLAYERS * 256 * 256];
__device__ __align__(128) __nv_bfloat16 g_WvalT_lo [NLAYERS * 256 * 256];
__device__ __align__(128) __nv_bfloat16 g_WcombT_hi[NLAYERS * 384 * 256];
__device__ __align__(128) __nv_bfloat16 g_WcombT_lo[NLAYERS * 384 * 256];
__device__ __align__(128) __nv_bfloat16 g_WoutT_hi [NLAYERS * 256 * 256];
__device__ __align__(128) __nv_bfloat16 g_WoutT_lo [NLAYERS * 256 * 256];
__device__ __align__(128) __nv_bfloat16 g_W1T_hi   [NLAYERS * 1024 * 256];
__device__ __align__(128) __nv_bfloat16 g_W1T_lo   [NLAYERS * 1024 * 256];
__device__ __align__(128) __nv_bfloat16 g_W2T_hi   [NLAYERS * 256 * 1024];
__device__ __align__(128) __nv_bfloat16 g_W2T_lo   [NLAYERS * 256 * 1024];
__device__ __align__(128) float g_bcomb[NLAYERS * 384];

// ---------------------------------------------------------------------------
// helpers
// ---------------------------------------------------------------------------
__device__ __forceinline__ uint32_t smem_u32(const void* p) {
    uint32_t a;
    asm("{ .reg .u64 t; cvta.to.shared.u64 t, %1; cvt.u32.u64 %0, t; }" : "=r"(a) : "l"(p));
    return a;
}
__device__ __forceinline__ void level_of_s(int s, int& lvl, int& start, int& hh, int& ww) {
    if (s < 16384)      { lvl = 0; start = 0;     hh = 128; ww = 128; }
    else if (s < 20480) { lvl = 1; start = 16384; hh = 64;  ww = 64;  }
    else if (s < 21504) { lvl = 2; start = 20480; hh = 32;  ww = 32;  }
    else                { lvl = 3; start = 21504; hh = 16;  ww = 16;  }
}
__device__ __forceinline__ void split_bf16(float v, __nv_bfloat16& h, __nv_bfloat16& l) {
    h = __float2bfloat16(v);
    l = __float2bfloat16(v - __bfloat162float(h));
}

// ---------------------------------------------------------------------------
// Weight preprocessing: out[n*K + k] = split(W[k*N + n])
// ---------------------------------------------------------------------------
__global__ void wsplit_kernel(const float* __restrict__ W,
                              __nv_bfloat16* __restrict__ hi, __nv_bfloat16* __restrict__ lo,
                              int K, int N) {
    int idx = blockIdx.x * blockDim.x + threadIdx.x;
    if (idx >= K * N) return;
    int k = idx % K, n = idx / K;
    float a = W[(size_t)k * N + n];
    __nv_bfloat16 h, l;
    split_bf16(a, h, l);
    hi[idx] = h; lo[idx] = l;
}

__global__ void bcomb_kernel(const float* __restrict__ boff, const float* __restrict__ battn) {
    int i = blockIdx.x * blockDim.x + threadIdx.x;
    if (i >= NLAYERS * 384) return;
    int l = i / 384, c = i % 384;
    g_bcomb[i] = (c < 256) ? boff[l * 256 + c] : battn[l * 128 + (c - 256)];
}

// ---------------------------------------------------------------------------
// Flatten: g_out, g_pos fp32 + out hi/lo + q=out+pos hi/lo
// ---------------------------------------------------------------------------
__global__ void flatten_kernel(const float* __restrict__ s0, const float* __restrict__ s1,
                               const float* __restrict__ s2, const float* __restrict__ s3,
                               const float* __restrict__ p0, const float* __restrict__ p1,
                               const float* __restrict__ p2, const float* __restrict__ p3,
                               const float* __restrict__ le) {
    size_t idx = (size_t)blockIdx.x * blockDim.x + threadIdx.x;
    size_t total = (size_t)M_ROWS * D;
    if (idx >= total) return;
    int d = (int)(idx % D);
    int bs = (int)(idx / D);
    int s = bs % S_TOTAL;
    int b = bs / S_TOTAL;
    int lvl, start, hh, ww;
    level_of_s(s, lvl, start, hh, ww);
    int local = s - start;
    int y = local / ww;
    int x = local % ww;
    const float* sp; const float* pp;
    switch (lvl) {
        case 0: sp = s0; pp = p0; break;
        case 1: sp = s1; pp = p1; break;
        case 2: sp = s2; pp = p2; break;
        default: sp = s3; pp = p3; break;
    }
    size_t off = (((size_t)b * D + d) * hh + y) * ww + x;
    float ov = sp[off];
    float pv = pp[off] + le[lvl * D + d];
    g_out[idx] = ov;
    g_pos[idx] = pv;
    __nv_bfloat16 h, l;
    split_bf16(ov, h, l);
    g_out_hi[idx] = h; g_out_lo[idx] = l;
    split_bf16(ov + pv, h, l);
    g_q_hi[idx] = h; g_q_lo[idx] = l;
}

// ---------------------------------------------------------------------------
// Tensor-core GEMM via legacy mma.sync bf16 (3-term hi/lo decomposition):
//   C[M,N] = A @ B^T + bias, A hi/lo [M,K] bf16, B hi/lo [N,K] bf16.
// BM=BN=128, BK=32; 256 threads = 8 warps (2m x 4n), warp tile 64x32.
// Double-buffered cp.async; XOR-swizzled smem (conflict-free ldmatrix).
// ---------------------------------------------------------------------------
#define GM_SMEM 65536   // 2 stages x (4 tiles x 128 rows x 64B)

__device__ __forceinline__ uint32_t swz(int row, int g) {
    return (uint32_t)(row * 64) + (uint32_t)((g ^ ((row >> 1) & 3)) << 4);
}

template <bool RELU, bool BF16OUT>
__global__ void __launch_bounds__(256)
gemm_mma(const __nv_bfloat16* __restrict__ Ahi, const __nv_bfloat16* __restrict__ Alo,
         const __nv_bfloat16* __restrict__ Bhi, const __nv_bfloat16* __restrict__ Blo,
         const float* __restrict__ bias,
         float* __restrict__ Cf, __nv_bfloat16* __restrict__ Chi, __nv_bfloat16* __restrict__ Clo,
         int N, int K) {
    extern __shared__ char smem[];
    const uint32_t sb = smem_u32(smem);
    const int tid = threadIdx.x;
    const int lane = tid & 31;
    const int wid = tid >> 5;
    const int bm = blockIdx.y * 128;
    const int bn = blockIdx.x * 128;
    const int wm = (wid >> 2) * 64;    // 0 / 64
    const int wn = (wid & 3) * 32;     // 0,32,64,96
    const int nk = K >> 5;

    float acc[4][4][4];
    #pragma unroll
    for (int i = 0; i < 4; ++i)
        #pragma unroll
        for (int j = 0; j < 4; ++j)
            #pragma unroll
            for (int r = 0; r < 4; ++r) acc[i][j][r] = 0.f;

    auto issue = [&](int st, int kt) {
        uint32_t base = sb + (uint32_t)st * 32768u;
        #pragma unroll
        for (int t = 0; t < 2; ++t) {
            int j = tid + t * 256;
            int row = j >> 2, gc = j & 3;
            uint32_t off = swz(row, gc);
            size_t ak = (size_t)(bm + row) * K + kt * 32 + gc * 8;
            size_t bk = (size_t)(bn + row) * K + kt * 32 + gc * 8;
            asm volatile("cp.async.cg.shared.global [%0], [%1], 16;" :: "r"(base + off),          "l"(Ahi + ak));
            asm volatile("cp.async.cg.shared.global [%0], [%1], 16;" :: "r"(base + 8192u + off),  "l"(Alo + ak));
            asm volatile("cp.async.cg.shared.global [%0], [%1], 16;" :: "r"(base + 16384u + off), "l"(Bhi + bk));
            asm volatile("cp.async.cg.shared.global [%0], [%1], 16;" :: "r"(base + 24576u + off), "l"(Blo + bk));
        }
        asm volatile("cp.async.commit_group;");
    };

    issue(0, 0);

    for (int kt = 0; kt < nk; ++kt) {
        const bool more = (kt + 1 < nk);
        if (more) issue((kt + 1) & 1, kt + 1);
        if (more) asm volatile("cp.async.wait_group 1;");
        else      asm volatile("cp.async.wait_group 0;");
        __syncthreads();

        uint32_t base = sb + (uint32_t)(kt & 1) * 32768u;
        #pragma unroll
        for (int ks = 0; ks < 2; ++ks) {
            uint32_t ah[4][4], al[4][4], bh[4][2], bl[4][2];
            #pragma unroll
            for (int im = 0; im < 4; ++im) {
                int r = wm + im * 16 + (lane & 15);
                int g = (ks << 1) + (lane >> 4);
                uint32_t adr = base + swz(r, g);
                asm volatile("ldmatrix.sync.aligned.m8n8.x4.shared.b16 {%0,%1,%2,%3}, [%4];"
                             : "=r"(ah[im][0]), "=r"(ah[im][1]), "=r"(ah[im][2]), "=r"(ah[im][3]) : "r"(adr));
                asm volatile("ldmatrix.sync.aligned.m8n8.x4.shared.b16 {%0,%1,%2,%3}, [%4];"
                             : "=r"(al[im][0]), "=r"(al[im][1]), "=r"(al[im][2]), "=r"(al[im][3]) : "r"(adr + 8192u));
            }
            #pragma unroll
            for (int in = 0; in < 4; ++in) {
                int r = wn + in * 8 + (lane & 7);
                int g = (ks << 1) + ((lane >> 3) & 1);
                uint32_t adr = base + 16384u + swz(r, g);
                asm volatile("ldmatrix.sync.aligned.m8n8.x2.shared.b16 {%0,%1}, [%2];"
                             : "=r"(bh[in][0]), "=r"(bh[in][1]) : "r"(adr));
                asm volatile("ldmatrix.sync.aligned.m8n8.x2.shared.b16 {%0,%1}, [%2];"
                             : "=r"(bl[in][0]), "=r"(bl[in][1]) : "r"(adr + 8192u));
            }
            #pragma unroll
            for (int im = 0; im < 4; ++im) {
                #pragma unroll
                for (int in = 0; in < 4; ++in) {
                    float* c = acc[im][in];
                    asm volatile("mma.sync.aligned.m16n8k16.row.col.f32.bf16.bf16.f32 "
                                 "{%0,%1,%2,%3},{%4,%5,%6,%7},{%8,%9},{%0,%1,%2,%3};"
                                 : "+f"(c[0]), "+f"(c[1]), "+f"(c[2]), "+f"(c[3])
                                 : "r"(ah[im][0]), "r"(ah[im][1]), "r"(ah[im][2]), "r"(ah[im][3]),
                                   "r"(bh[in][0]), "r"(bh[in][1]));
                    asm volatile("mma.sync.aligned.m16n8k16.row.col.f32.bf16.bf16.f32 "
                                 "{%0,%1,%2,%3},{%4,%5,%6,%7},{%8,%9},{%0,%1,%2,%3};"
                                 : "+f"(c[0]), "+f"(c[1]), "+f"(c[2]), "+f"(c[3])
                                 : "r"(ah[im][0]), "r"(ah[im][1]), "r"(ah[im][2]), "r"(ah[im][3]),
                                   "r"(bl[in][0]), "r"(bl[in][1]));
                    asm volatile("mma.sync.aligned.m16n8k16.row.col.f32.bf16.bf16.f32 "
                                 "{%0,%1,%2,%3},{%4,%5,%6,%7},{%8,%9},{%0,%1,%2,%3};"
                                 : "+f"(c[0]), "+f"(c[1]), "+f"(c[2]), "+f"(c[3])
                                 : "r"(al[im][0]), "r"(al[im][1]), "r"(al[im][2]), "r"(al[im][3]),
                                   "r"(bh[in][0]), "r"(bh[in][1]));
                }
            }
        }
        __syncthreads();
    }

    // epilogue
    const int r0 = bm + wm + (lane >> 2);
    const int c0 = bn + wn + (lane & 3) * 2;
    #pragma unroll
    for (int im = 0; im < 4; ++im) {
        #pragma unroll
        for (int in = 0; in < 4; ++in) {
            int r = r0 + im * 16;
            int c = c0 + in * 8;
            float b0 = bias[c], b1 = bias[c + 1];
            float v0 = acc[im][in][0] + b0;
            float v1 = acc[im][in][1] + b1;
            float v2 = acc[im][in][2] + b0;
            float v3 = acc[im][in][3] + b1;
            if (RELU) {
                v0 = fmaxf(v0, 0.f); v1 = fmaxf(v1, 0.f);
                v2 = fmaxf(v2, 0.f); v3 = fmaxf(v3, 0.f);
            }
            if (BF16OUT) {
                __nv_bfloat16 h0, l0, h1, l1;
                split_bf16(v0, h0, l0); split_bf16(v1, h1, l1);
                uint32_t ph = (uint32_t)__bfloat16_as_ushort(h0) | ((uint32_t)__bfloat16_as_ushort(h1) << 16);
                uint32_t pl = (uint32_t)__bfloat16_as_ushort(l0) | ((uint32_t)__bfloat16_as_ushort(l1) << 16);
                *reinterpret_cast<uint32_t*>(Chi + (size_t)r * N + c) = ph;
                *reinterpret_cast<uint32_t*>(Clo + (size_t)r * N + c) = pl;
                split_bf16(v2, h0, l0); split_bf16(v3, h1, l1);
                ph = (uint32_t)__bfloat16_as_ushort(h0) | ((uint32_t)__bfloat16_as_ushort(h1) << 16);
                pl = (uint32_t)__bfloat16_as_ushort(l0) | ((uint32_t)__bfloat16_as_ushort(l1) << 16);
                *reinterpret_cast<uint32_t*>(Chi + (size_t)(r + 8) * N + c) = ph;
                *reinterpret_cast<uint32_t*>(Clo + (size_t)(r + 8) * N + c) = pl;
            } else {
                *reinterpret_cast<float2*>(Cf + (size_t)r * N + c) = make_float2(v0, v1);
                *reinterpret_cast<float2*>(Cf + (size_t)(r + 8) * N + c) = make_float2(v2, v3);
            }
        }
    }
}

// ---------------------------------------------------------------------------
// softmax over 16 logits per (b,s,h) — in g_offattn at col offset 256
// ---------------------------------------------------------------------------
__global__ void softmax16_kernel() {
    int idx = blockIdx.x * blockDim.x + threadIdx.x;
    if (idx >= M_ROWS * NH) return;
    int bs = idx >> 3;
    int h = idx & 7;
    float* p = g_offattn + (size_t)bs * 384 + 256 + h * 16;
    float v[16];
    float mx = -1e30f;
    #pragma unroll
    for (int i = 0; i < 16; ++i) { v[i] = p[i]; mx = fmaxf(mx, v[i]); }
    float sum = 0.f;
    #pragma unroll
    for (int i = 0; i < 16; ++i) { v[i] = expf(v[i] - mx); sum += v[i]; }
    float inv = 1.f / sum;
    #pragma unroll
    for (int i = 0; i < 16; ++i) p[i] = v[i] * inv;
}

// ---------------------------------------------------------------------------
// MS-deform sampling: warp per (b,s,h), lane = channel; writes attn hi/lo
// ---------------------------------------------------------------------------
__global__ __launch_bounds__(256)
void sample_kernel() {
    int warp = (blockIdx.x * blockDim.x + threadIdx.x) >> 5;
    int lane = threadIdx.x & 31;
    if (warp >= M_ROWS * NH) return;
    int h = warp & 7;
    int bs = warp >> 3;
    int b = bs / S_TOTAL;
    int s = bs - b * S_TOTAL;

    int qlvl, qstart, qh, qw;
    level_of_s(s, qlvl, qstart, qh, qw);
    int qlocal = s - qstart;
    int qy = qlocal / qw;
    int qx = qlocal - qy * qw;
    float ref_x = (qx + 0.5f) / (float)qw;
    float ref_y = (qy + 0.5f) / (float)qh;

    const float* offp = g_offattn + (size_t)bs * 384 + h * 32;
    const float* awp  = g_offattn + (size_t)bs * 384 + 256 + h * 16;
    const float* valb = g_value + (size_t)b * S_TOTAL * D + h * DH + lane;

    float acc = 0.f;
    #pragma unroll
    for (int l = 0; l < NL; ++l) {
        int H = c_lvl_h[l], W = c_lvl_w[l], start = c_lvl_start[l];
        float fW = (float)W, fH = (float)H;
        #pragma unroll
        for (int p = 0; p < NP; ++p) {
            float ox = offp[l * 8 + p * 2 + 0];
            float oy = offp[l * 8 + p * 2 + 1];
            float aw = awp[l * 4 + p];
            float x = (ref_x + ox / fW) * fW - 0.5f;
            float y = (ref_y + oy / fH) * fH - 0.5f;
            float x0f = floorf(x), y0f = floorf(y);
            float lx = x - x0f, ly = y - y0f;
            int x0 = (int)x0f, y0 = (int)y0f;
            int x1 = x0 + 1, y1 = y0 + 1;
            bool vx0 = (x0 >= 0) & (x0 < W);
            bool vx1 = (x1 >= 0) & (x1 < W);
            bool vy0 = (y0 >= 0) & (y0 < H);
            bool vy1 = (y1 >= 0) & (y1 < H);
            float v00 = 0.f, v10 = 0.f, v01 = 0.f, v11 = 0.f;
            if (vx0 & vy0) v00 = valb[(size_t)(start + y0 * W + x0) * D];
            if (vx1 & vy0) v10 = valb[(size_t)(start + y0 * W + x1) * D];
            if (vx0 & vy1) v01 = valb[(size_t)(start + y1 * W + x0) * D];
            if (vx1 & vy1) v11 = valb[(size_t)(start + y1 * W + x1) * D];
            float samp = (1.f - lx) * (1.f - ly) * v00
                       + lx * (1.f - ly) * v10
                       + (1.f - lx) * ly * v01
                       + lx * ly * v11;
            acc = fmaf(aw, samp, acc);
        }
    }
    size_t oidx = (size_t)bs * D + h * DH + lane;
    __nv_bfloat16 hh, ll;
    split_bf16(acc, hh, ll);
    g_attn_hi[oidx] = hh;
    g_attn_lo[oidx] = ll;
}

// ---------------------------------------------------------------------------
// dst = LayerNorm(x + y); optional bf16 hi/lo of dst; optional q=dst+pos hi/lo
// ---------------------------------------------------------------------------
__global__ __launch_bounds__(256)
void residual_ln_kernel(const float* __restrict__ x, const float* __restrict__ y,
                        const float* __restrict__ gamma, const float* __restrict__ beta,
                        float* __restrict__ dst,
                        __nv_bfloat16* __restrict__ dhi, __nv_bfloat16* __restrict__ dlo,
                        const float* __restrict__ pos,
                        __nv_bfloat16* __restrict__ qhi, __nv_bfloat16* __restrict__ qlo) {
    int row = (blockIdx.x * blockDim.x + threadIdx.x) >> 5;
    int lane = threadIdx.x & 31;
    if (row >= M_ROWS) return;
    const float* xr = x + (size_t)row * D + lane * 8;
    const float* yr = y + (size_t)row * D + lane * 8;
    float v[8];
    float s = 0.f;
    #pragma unroll
    for (int i = 0; i < 8; ++i) { v[i] = xr[i] + yr[i]; s += v[i]; }
    #pragma unroll
    for (int o = 16; o > 0; o >>= 1) s += __shfl_xor_sync(0xffffffffu, s, o);
    float mean = s * (1.f / D);
    float vs = 0.f;
    #pragma unroll
    for (int i = 0; i < 8; ++i) { float d = v[i] - mean; vs += d * d; }
    #pragma unroll
    for (int o = 16; o > 0; o >>= 1) vs += __shfl_xor_sync(0xffffffffu, vs, o);
    float rstd = rsqrtf(vs * (1.f / D) + 1e-5f);

    size_t base = (size_t)row * D + lane * 8;
    float* dr = dst + base;
    float w[8];
    #pragma unroll
    for (int i = 0; i < 8; ++i) {
        int c = lane * 8 + i;
        w[i] = (v[i] - mean) * rstd * gamma[c] + beta[c];
        dr[i] = w[i];
    }
    if (dhi) {
        uint32_t ph[4], pl[4];
        #pragma unroll
        for (int p = 0; p < 4; ++p) {
            __nv_bfloat16 h0, l0, h1, l1;
            split_bf16(w[2 * p], h0, l0);
            split_bf16(w[2 * p + 1], h1, l1);
            ph[p] = (uint32_t)__bfloat16_as_ushort(h0) | ((uint32_t)__bfloat16_as_ushort(h1) << 16);
            pl[p] = (uint32_t)__bfloat16_as_ushort(l0) | ((uint32_t)__bfloat16_as_ushort(l1) << 16);
        }
        *reinterpret_cast<uint4*>(dhi + base) = make_uint4(ph[0], ph[1], ph[2], ph[3]);
        *reinterpret_cast<uint4*>(dlo + base) = make_uint4(pl[0], pl[1], pl[2], pl[3]);
    }
    if (qhi) {
        const float* pr = pos + base;
        uint32_t ph[4], pl[4];
        #pragma unroll
        for (int p = 0; p < 4; ++p) {
            __nv_bfloat16 h0, l0, h1, l1;
            split_bf16(w[2 * p] + pr[2 * p], h0, l0);
            split_bf16(w[2 * p + 1] + pr[2 * p + 1], h1, l1);
            ph[p] = (uint32_t)__bfloat16_as_ushort(h0) | ((uint32_t)__bfloat16_as_ushort(h1) << 16);
            pl[p] = (uint32_t)__bfloat16_as_ushort(l0) | ((uint32_t)__bfloat16_as_ushort(l1) << 16);
        }
        *reinterpret_cast<uint4*>(qhi + base) = make_uint4(ph[0], ph[1], ph[2], ph[3]);
        *reinterpret_cast<uint4*>(qlo + base) = make_uint4(pl[0], pl[1], pl[2], pl[3]);
    }
}

// ---------------------------------------------------------------------------
// host launcher
// ---------------------------------------------------------------------------
extern "C" void kernel_launch(void* const* d_in, const int* in_sizes, int n_in,
                              void* d_out, int out_size) {
    const int lvl_elems[NL] = {
        BATCH * D * 128 * 128, BATCH * D * 64 * 64,
        BATCH * D * 32 * 32,   BATCH * D * 16 * 16
    };
    const float* srcp[NL] = {0, 0, 0, 0};
    const float* posp[NL] = {0, 0, 0, 0};
    for (int i = 0; i < 8; ++i) {
        int sz = in_sizes[i];
        for (int l = 0; l < NL; ++l) {
            if (sz == lvl_elems[l]) {
                if (!srcp[l]) srcp[l] = (const float*)d_in[i];
                else if (!posp[l]) posp[l] = (const float*)d_in[i];
                break;
            }
        }
    }

    const float* level_embed = (const float*)d_in[8];
    const float* Woff  = (const float*)d_in[9];
    const float* boff  = (const float*)d_in[10];
    const float* Wattn = (const float*)d_in[11];
    const float* battn = (const float*)d_in[12];
    const float* Wval  = (const float*)d_in[13];
    const float* bval  = (const float*)d_in[14];
    const float* Wout  = (const float*)d_in[15];
    const float* bout  = (const float*)d_in[16];
    const float* ln1_s = (const float*)d_in[17];
    const float* ln1_b = (const float*)d_in[18];
    const float* W1    = (const float*)d_in[19];
    const float* b1    = (const float*)d_in[20];
    const float* W2    = (const float*)d_in[21];
    const float* b2    = (const float*)d_in[22];
    const float* ln2_s = (const float*)d_in[23];
    const float* ln2_b = (const float*)d_in[24];
    float* out = (float*)d_out;

    float *p_pos, *p_out, *p_value, *p_offattn, *p_proj, *p_ffn2, *p_bcomb;
    __nv_bfloat16 *p_out_hi, *p_out_lo, *p_q_hi, *p_q_lo, *p_ln1_hi, *p_ln1_lo,
                  *p_attn_hi, *p_attn_lo, *p_f1_hi, *p_f1_lo;
    __nv_bfloat16 *p_WvalT_hi, *p_WvalT_lo, *p_WcombT_hi, *p_WcombT_lo,
                  *p_WoutT_hi, *p_WoutT_lo, *p_W1T_hi, *p_W1T_lo, *p_W2T_hi, *p_W2T_lo;
    cudaGetSymbolAddress((void**)&p_pos, g_pos);
    cudaGetSymbolAddress((void**)&p_out, g_out);
    cudaGetSymbolAddress((void**)&p_value, g_value);
    cudaGetSymbolAddress((void**)&p_offattn, g_offattn);
    cudaGetSymbolAddress((void**)&p_proj, g_proj);
    cudaGetSymbolAddress((void**)&p_ffn2, g_ffn2);
    cudaGetSymbolAddress((void**)&p_bcomb, g_bcomb);
    cudaGetSymbolAddress((void**)&p_out_hi, g_out_hi);
    cudaGetSymbolAddress((void**)&p_out_lo, g_out_lo);
    cudaGetSymbolAddress((void**)&p_q_hi, g_q_hi);
    cudaGetSymbolAddress((void**)&p_q_lo, g_q_lo);
    cudaGetSymbolAddress((void**)&p_ln1_hi, g_ln1_hi);
    cudaGetSymbolAddress((void**)&p_ln1_lo, g_ln1_lo);
    cudaGetSymbolAddress((void**)&p_attn_hi, g_attn_hi);
    cudaGetSymbolAddress((void**)&p_attn_lo, g_attn_lo);
    cudaGetSymbolAddress((void**)&p_f1_hi, g_f1_hi);
    cudaGetSymbolAddress((void**)&p_f1_lo, g_f1_lo);
    cudaGetSymbolAddress((void**)&p_WvalT_hi, g_WvalT_hi);
    cudaGetSymbolAddress((void**)&p_WvalT_lo, g_WvalT_lo);
    cudaGetSymbolAddress((void**)&p_WcombT_hi, g_WcombT_hi);
    cudaGetSymbolAddress((void**)&p_WcombT_lo, g_WcombT_lo);
    cudaGetSymbolAddress((void**)&p_WoutT_hi, g_WoutT_hi);
    cudaGetSymbolAddress((void**)&p_WoutT_lo, g_WoutT_lo);
    cudaGetSymbolAddress((void**)&p_W1T_hi, g_W1T_hi);
    cudaGetSymbolAddress((void**)&p_W1T_lo, g_W1T_lo);
    cudaGetSymbolAddress((void**)&p_W2T_hi, g_W2T_hi);
    cudaGetSymbolAddress((void**)&p_W2T_lo, g_W2T_lo);

    cudaFuncSetAttribute(gemm_mma<false, false>, cudaFuncAttributeMaxDynamicSharedMemorySize, GM_SMEM);
    cudaFuncSetAttribute(gemm_mma<true, true>,   cudaFuncAttributeMaxDynamicSharedMemorySize, GM_SMEM);

    const int TB = 256;
    const size_t total = (size_t)M_ROWS * D;
    const int elem_blocks = (int)((total + TB - 1) / TB);

    // ---- weight preprocessing ----
    for (int i = 0; i < NLAYERS; ++i) {
        wsplit_kernel<<<(256 * 256 + 255) / 256, 256>>>(Wval + (size_t)i * 256 * 256,
            p_WvalT_hi + (size_t)i * 256 * 256, p_WvalT_lo + (size_t)i * 256 * 256, 256, 256);
        wsplit_kernel<<<(256 * 256 + 255) / 256, 256>>>(Woff + (size_t)i * 256 * 256,
            p_WcombT_hi + (size_t)i * 384 * 256, p_WcombT_lo + (size_t)i * 384 * 256, 256, 256);
        wsplit_kernel<<<(256 * 128 + 255) / 256, 256>>>(Wattn + (size_t)i * 256 * 128,
            p_WcombT_hi + (size_t)i * 384 * 256 + 256 * 256,
            p_WcombT_lo + (size_t)i * 384 * 256 + 256 * 256, 256, 128);
        wsplit_kernel<<<(256 * 256 + 255) / 256, 256>>>(Wout + (size_t)i * 256 * 256,
            p_WoutT_hi + (size_t)i * 256 * 256, p_WoutT_lo + (size_t)i * 256 * 256, 256, 256);
        wsplit_kernel<<<(256 * 1024 + 255) / 256, 256>>>(W1 + (size_t)i * 256 * 1024,
            p_W1T_hi + (size_t)i * 1024 * 256, p_W1T_lo + (size_t)i * 1024 * 256, 256, 1024);
        wsplit_kernel<<<(1024 * 256 + 255) / 256, 256>>>(W2 + (size_t)i * 1024 * 256,
            p_W2T_hi + (size_t)i * 256 * 1024, p_W2T_lo + (size_t)i * 256 * 1024, 1024, 256);
    }
    bcomb_kernel<<<(NLAYERS * 384 + 255) / 256, 256>>>(boff, battn);

    flatten_kernel<<<elem_blocks, TB>>>(srcp[0], srcp[1], srcp[2], srcp[3],
                                        posp[0], posp[1], posp[2], posp[3], level_embed);

    const dim3 gblk(256);
    for (int i = 0; i < NLAYERS; ++i) {
        // value = out @ Wval + bval
        gemm_mma<false, false><<<dim3(2, M_ROWS / 128), gblk, GM_SMEM>>>(
            p_out_hi, p_out_lo,
            p_WvalT_hi + (size_t)i * 256 * 256, p_WvalT_lo + (size_t)i * 256 * 256,
            bval + (size_t)i * 256, p_value, 0, 0, 256, 256);
        // [off | attn] = q @ Wcomb + bcomb
        gemm_mma<false, false><<<dim3(3, M_ROWS / 128), gblk, GM_SMEM>>>(
            p_q_hi, p_q_lo,
            p_WcombT_hi + (size_t)i * 384 * 256, p_WcombT_lo + (size_t)i * 384 * 256,
            p_bcomb + (size_t)i * 384, p_offattn, 0, 0, 384, 256);
        // softmax over 16
        softmax16_kernel<<<(M_ROWS * NH + TB - 1) / TB, TB>>>();
        // deform sampling -> attn hi/lo
        sample_kernel<<<(M_ROWS * NH * 32 + TB - 1) / TB, TB>>>();
        // proj = attnout @ Wout + bout
        gemm_mma<false, false><<<dim3(2, M_ROWS / 128), gblk, GM_SMEM>>>(
            p_attn_hi, p_attn_lo,
            p_WoutT_hi + (size_t)i * 256 * 256, p_WoutT_lo + (size_t)i * 256 * 256,
            bout + (size_t)i * 256, p_proj, 0, 0, 256, 256);
        // out = LN(out + proj), + ln1 hi/lo
        residual_ln_kernel<<<(M_ROWS * 32 + TB - 1) / TB, TB>>>(
            p_out, p_proj, ln1_s + (size_t)i * 256, ln1_b + (size_t)i * 256,
            p_out, p_ln1_hi, p_ln1_lo, (const float*)0, (__nv_bfloat16*)0, (__nv_bfloat16*)0);
        // ffn1 = relu(ln1 @ W1 + b1) -> bf16 hi/lo
        gemm_mma<true, true><<<dim3(8, M_ROWS / 128), gblk, GM_SMEM>>>(
            p_ln1_hi, p_ln1_lo,
            p_W1T_hi + (size_t)i * 1024 * 256, p_W1T_lo + (size_t)i * 1024 * 256,
            b1 + (size_t)i * 1024, (float*)0, p_f1_hi, p_f1_lo, 1024, 256);
        // ffn2 = ffn1 @ W2 + b2
        gemm_mma<false, false><<<dim3(2, M_ROWS / 128), gblk, GM_SMEM>>>(
            p_f1_hi, p_f1_lo,
            p_W2T_hi + (size_t)i * 256 * 1024, p_W2T_lo + (size_t)i * 256 * 1024,
            b2 + (size_t)i * 256, p_ffn2, 0, 0, 256, 1024);
        // out = LN(out + ffn2); intermediate layers also emit out hi/lo + q hi/lo
        if (i == NLAYERS - 1) {
            residual_ln_kernel<<<(M_ROWS * 32 + TB - 1) / TB, TB>>>(
                p_out, p_ffn2, ln2_s + (size_t)i * 256, ln2_b + (size_t)i * 256,
                out, (__nv_bfloat16*)0, (__nv_bfloat16*)0,
                (const float*)0, (__nv_bfloat16*)0, (__nv_bfloat16*)0);
        } else {
            residual_ln_kernel<<<(M_ROWS * 32 + TB - 1) / TB, TB>>>(
                p_out, p_ffn2, ln2_s + (size_t)i * 256, ln2_b + (size_t)i * 256,
                p_out, p_out_hi, p_out_lo, p_pos, p_q_hi, p_q_lo);
        }
    }
}